// round 10
// baseline (speedup 1.0000x reference)
#include <cuda_runtime.h>
#include <cstdint>

#define NA    57600     // 64*100*9 anchors
#define NLOC  6400      // 64*100
#define FW    100
#define PRE   6000
#define POST  300
#define NW    94        // ceil(6000/64) u64 words
#define CAP   8192
#define NBIN  65536
#define NCO   1024
#define FULL  0xFFFFFFFFu
#define LOOK  16

typedef unsigned long long u64;

// Base anchors (ratios 0.5,1,2 x scales 8,16,32), numpy banker's rounding baked in.
__constant__ float c_base[36] = {
  -84.f,  -40.f,  99.f,  55.f,
 -176.f,  -88.f, 191.f, 103.f,
 -360.f, -184.f, 375.f, 199.f,
  -56.f,  -56.f,  71.f,  71.f,
 -120.f, -120.f, 135.f, 135.f,
 -248.f, -248.f, 263.f, 263.f,
  -36.f,  -80.f,  51.f,  95.f,
  -80.f, -168.f,  95.f, 183.f,
 -168.f, -344.f, 183.f, 359.f
};

// NOTE: g_hist/g_coarse/g_rank/g_cnt must be ZERO on entry to each run.
// They start zero (static init) and are re-zeroed by k_mask each run.
__device__ float4   g_boxes[NA];
__device__ unsigned g_keys[NA];
__device__ unsigned g_hist[NBIN];
__device__ unsigned g_coarse[NCO];
__device__ int      g_cnt;
__device__ unsigned g_B;
__device__ u64      g_cand[CAP];
__device__ int      g_rank[CAP];
__device__ float4   g_top[PRE];
__device__ u64      g_mask[(size_t)PRE * NW];   // triangular: words < i/64 of row i NOT written
__device__ float    g_probe[POST * 5];          // scratch output for the profiling probe

// ---------------------------------------------------------------- decode + fine/coarse histograms
__global__ void k_decode(const float* __restrict__ cls,
                         const float* __restrict__ bbox,
                         const int*   __restrict__ ih,
                         const int*   __restrict__ iw) {
    int t = blockIdx.x * blockDim.x + threadIdx.x;
    if (t >= NA) return;
    int a = t / NLOC, loc = t % NLOC;       // coalesced channel reads
    int y = loc / FW, x = loc % FW;
    int ai = loc * 9 + a;                   // reference anchor index

    float s0 = cls[(2 * a)     * NLOC + loc];
    float s1 = cls[(2 * a + 1) * NLOC + loc];
    float m  = fmaxf(s0, s1);
    float e0 = expf(s0 - m), e1 = expf(s1 - m);
    float score = e1 / (e0 + e1);

    float dx = bbox[(4 * a + 0) * NLOC + loc];
    float dy = bbox[(4 * a + 1) * NLOC + loc];
    float dw = bbox[(4 * a + 2) * NLOC + loc];
    float dh = bbox[(4 * a + 3) * NLOC + loc];

    float sx = (float)(x * 16), sy = (float)(y * 16);
    float ax1 = sx + c_base[a * 4 + 0];
    float ay1 = sy + c_base[a * 4 + 1];
    float ax2 = sx + c_base[a * 4 + 2];
    float ay2 = sy + c_base[a * 4 + 3];

    float w  = ax2 - ax1 + 1.0f;
    float h  = ay2 - ay1 + 1.0f;
    float cx = ax1 + 0.5f * w;
    float cy = ay1 + 0.5f * h;

    float pcx = dx * w + cx;
    float pcy = dy * h + cy;
    float pw  = expf(dw) * w;
    float ph  = expf(dh) * h;

    float W = (float)(iw[0] - 1);
    float H = (float)(ih[0] - 1);
    float x1 = fminf(fmaxf(pcx - 0.5f * pw, 0.f), W);
    float y1 = fminf(fmaxf(pcy - 0.5f * ph, 0.f), H);
    float x2 = fminf(fmaxf(pcx + 0.5f * pw, 0.f), W);
    float y2 = fminf(fmaxf(pcy + 0.5f * ph, 0.f), H);

    bool valid = (x2 - x1 + 1.f >= 16.f) && (y2 - y1 + 1.f >= 16.f);
    float s = valid ? score : -1e30f;

    unsigned u = __float_as_uint(s);
    unsigned key = (u & 0x80000000u) ? ~u : (u | 0x80000000u);

    g_keys[t]   = key;
    g_boxes[ai] = make_float4(x1, y1, x2, y2);
    atomicAdd(&g_hist[key >> 16], 1u);
    atomicAdd(&g_coarse[key >> 22], 1u);
}

// ---------------------------------------------------------------- threshold bin via coarse hist (1 block)
__global__ void k_thresh() {
    __shared__ unsigned warpsum[32];
    __shared__ unsigned warpsuf[32];
    int t = threadIdx.x;            // 1024 threads, one per coarse bucket
    int lane = t & 31, warp = t >> 5;

    unsigned c = g_coarse[t];

    unsigned suf = c;
    #pragma unroll
    for (int off = 1; off < 32; off <<= 1) {
        unsigned v = __shfl_down_sync(FULL, suf, off);
        if (lane + off < 32) suf += v;
    }
    if (lane == 0) warpsum[warp] = suf;
    __syncthreads();
    if (warp == 0) {
        unsigned ws = warpsum[lane];
        unsigned s2 = ws;
        #pragma unroll
        for (int off = 1; off < 32; off <<= 1) {
            unsigned v = __shfl_down_sync(FULL, s2, off);
            if (lane + off < 32) s2 += v;
        }
        warpsuf[lane] = s2 - ws;
    }
    __syncthreads();

    unsigned suffInc = suf + warpsuf[warp];
    unsigned above   = suffInc - c;
    if (above < PRE && suffInc >= PRE) {
        unsigned run = above;
        int base = t * 64;          // coarse bucket t = fine bins [t*64, t*64+64)
        for (int b = 63; b >= 0; b--) {
            run += g_hist[base + b];
            if (run >= PRE) { g_B = (unsigned)(base + b); break; }
        }
    }
}

// ---------------------------------------------------------------- compact candidates (bin >= threshold bin)
__global__ void k_compact() {
    int t = blockIdx.x * blockDim.x + threadIdx.x;
    if (t >= NA) return;
    unsigned key = g_keys[t];
    if ((key >> 16) >= g_B) {
        int p = atomicAdd(&g_cnt, 1);
        if (p < CAP) {
            int a = t / NLOC, loc = t % NLOC;
            unsigned ai = (unsigned)(loc * 9 + a);
            g_cand[p] = ((u64)key << 32) | (~ai);
        }
    }
}

// ---------------------------------------------------------------- 2D-parallel exact rank (partial counts via atomics)
__global__ void k_rank2d() {
    __shared__ u64 tile[256];
    int cnt = g_cnt; if (cnt > CAP) cnt = CAP;
    if (blockIdx.x * 256 >= cnt || blockIdx.y * 256 >= cnt) return;  // uniform early exit
    int j = blockIdx.y * 256 + threadIdx.x;
    tile[threadIdx.x] = (j < cnt) ? g_cand[j] : 0ULL;   // zeros never beat valid keys
    __syncthreads();
    int p = blockIdx.x * 256 + threadIdx.x;
    if (p >= cnt) return;
    u64 v = g_cand[p];
    int r = 0;
    #pragma unroll 8
    for (int q = 0; q < 256; q++) r += (tile[q] > v);
    if (r) atomicAdd(&g_rank[p], r);
}

// ---------------------------------------------------------------- scatter boxes to rank order
__global__ void k_scatter() {
    int cnt = g_cnt; if (cnt > CAP) cnt = CAP;
    int p = blockIdx.x * 256 + threadIdx.x;
    if (p >= cnt) return;
    int r = g_rank[p];
    if (r < PRE) {
        u64 v = g_cand[p];
        unsigned idx = ~(unsigned)v;
        g_top[r] = g_boxes[idx];
    }
}

// ---------------------------------------------------------------- IoU bitmask (upper-triangular) + state re-zero
__global__ void k_mask() {
    __shared__ float4 sb[64];
    int cb = blockIdx.x, rb = blockIdx.y, t = threadIdx.x;

    // housekeeping for the NEXT run: zero hist/coarse/rank/cnt (safe: all
    // consumers of these ran in earlier kernels of THIS run)
    {
        int bid = blockIdx.y * gridDim.x + blockIdx.x;
        int gt  = bid * 64 + t;
        if (gt < NBIN)                       g_hist[gt] = 0u;
        else if (gt < NBIN + NCO)            g_coarse[gt - NBIN] = 0u;
        else if (gt < NBIN + NCO + CAP)      g_rank[gt - NBIN - NCO] = 0;
        else if (gt == NBIN + NCO + CAP)     g_cnt = 0;
    }

    if (cb < rb) return;           // sub-diagonal: never written, never read
    int i = rb * 64 + t;
    int j0 = cb * 64;
    int jg = j0 + t;
    sb[t] = (jg < PRE) ? g_top[jg] : make_float4(0.f, 0.f, 0.f, 0.f);
    __syncthreads();
    if (i >= PRE) return;
    float4 bi = g_top[i];
    float ai = (bi.z - bi.x) * (bi.w - bi.y);
    u64 bits = 0ULL;
    #pragma unroll 4
    for (int b = 0; b < 64; b++) {
        int j = j0 + b;
        float4 bj = sb[b];
        float aj = (bj.z - bj.x) * (bj.w - bj.y);
        float lx = fmaxf(bi.x, bj.x), ly = fmaxf(bi.y, bj.y);
        float rx = fminf(bi.z, bj.z), ry = fminf(bi.w, bj.w);
        float ww = fmaxf(rx - lx, 0.f), hh = fmaxf(ry - ly, 0.f);
        float inter = ww * hh;
        float iou = inter / (ai + aj - inter);
        if (j > i && j < PRE && iou > 0.7f) bits |= 1ULL << b;
    }
    g_mask[(size_t)i * NW + cb] = bits;
}

// ---------------------------------------------------------------- serial NMS core (shared by probe + real)
__device__ __forceinline__ void nms_run(float* __restrict__ out, int* s_keep) {
    int lane = threadIdx.x;        // 32 threads

    // lane owns words: lane, lane+32, lane+64  (valid words < 94)
    u64 rem0 = 0ULL, rem1 = 0ULL, rem2 = 0ULL;
    if (lane == 29) rem2 = (~0ULL) << 48;    // word 93: indices 6000..6015 invalid
    if (lane >= 30) rem2 = ~0ULL;            // words 94,95 don't exist

    int nk = 0;
    while (nk < POST) {
        // ---- free-word ballots (once per round)
        u64 f0 = ~rem0, f1 = ~rem1, f2 = ~rem2;
        unsigned b0 = __ballot_sync(FULL, f0 != 0ULL);
        unsigned b1 = __ballot_sync(FULL, f1 != 0ULL);
        unsigned b2 = __ballot_sync(FULL, f2 != 0ULL);

        // ---- pick first two free words (uniform)
        int wsel1 = -1, wsel2 = -1; u64 wfree1 = 0ULL, wfree2 = 0ULL;
        if (b0) {
            int src = __ffs(b0) - 1; wsel1 = src;
            wfree1 = __shfl_sync(FULL, f0, src);
            b0 &= b0 - 1;
        } else if (b1) {
            int src = __ffs(b1) - 1; wsel1 = src + 32;
            wfree1 = __shfl_sync(FULL, f1, src);
            b1 &= b1 - 1;
        } else if (b2) {
            int src = __ffs(b2) - 1; wsel1 = src + 64;
            wfree1 = __shfl_sync(FULL, f2, src);
            b2 &= b2 - 1;
        } else break;
        if (b0) {
            int src = __ffs(b0) - 1; wsel2 = src;
            wfree2 = __shfl_sync(FULL, f0, src);
        } else if (b1) {
            int src = __ffs(b1) - 1; wsel2 = src + 32;
            wfree2 = __shfl_sync(FULL, f1, src);
        } else if (b2) {
            int src = __ffs(b2) - 1; wsel2 = src + 64;
            wfree2 = __shfl_sync(FULL, f2, src);
        }

        // uniform live copies of the two active rem words
        u64 remw1 = ~wfree1;
        u64 remw2 = (wsel2 >= 0) ? ~wfree2 : ~0ULL;

        // ---- extract up to LOOK lowest free indices across the two words
        int j[LOOK];
        u64 t1 = wfree1, t2 = wfree2;
        #pragma unroll
        for (int m = 0; m < LOOK; m++) {
            if (t1) {
                int b = __ffsll((long long)t1) - 1;
                j[m] = (wsel1 << 6) + b;
                t1 &= t1 - 1;
            } else if (t2) {
                int b = __ffsll((long long)t2) - 1;
                j[m] = (wsel2 << 6) + b;
                t2 &= t2 - 1;
            } else j[m] = PRE;
        }

        // ---- prefetch candidate rows (triangular: clamp words < row start)
        u64 r0[LOOK], r1[LOOK], r2[LOOK];
        #pragma unroll
        for (int m = 0; m < LOOK; m++) {
            if (j[m] < PRE) {
                int sw = j[m] >> 6;
                const u64* row = g_mask + (size_t)j[m] * NW;
                r0[m] = (lane      >= sw)                   ? row[lane]      : 0ULL;
                r1[m] = (lane + 32 >= sw)                   ? row[lane + 32] : 0ULL;
                r2[m] = (lane + 64 >= sw && lane + 64 < NW) ? row[lane + 64] : 0ULL;
            } else { r0[m] = 0ULL; r1[m] = 0ULL; r2[m] = 0ULL; }
        }

        int slot1 = wsel1 >> 5, src1 = wsel1 & 31;
        int slot2 = (wsel2 >= 0) ? (wsel2 >> 5) : 0;
        int src2  = (wsel2 >= 0) ? (wsel2 & 31) : 0;

        // ---- decide candidates in ascending order (uniform control flow)
        #pragma unroll
        for (int m = 0; m < LOOK; m++) {
            int jm = j[m];
            if (jm >= PRE) break;
            int sw = jm >> 6;
            u64 bit = 1ULL << (jm & 63);
            bool inW1 = (sw == wsel1);
            if (inW1 ? (remw1 & bit) : (remw2 & bit)) continue;   // suppressed

            if (lane == 0) s_keep[nk] = jm;
            nk++;

            // broadcast row's two active words (prefetch already clamped)
            u64 val1 = (slot1 == 0) ? r0[m] : ((slot1 == 1) ? r1[m] : r2[m]);
            u64 rw1  = __shfl_sync(FULL, val1, src1);
            u64 rw2  = 0ULL;
            if (wsel2 >= 0) {
                u64 val2 = (slot2 == 0) ? r0[m] : ((slot2 == 1) ? r1[m] : r2[m]);
                rw2 = __shfl_sync(FULL, val2, src2);
            }
            remw1 |= rw1; remw2 |= rw2;
            if (inW1) remw1 |= bit; else remw2 |= bit;

            rem0 |= r0[m]; rem1 |= r1[m]; rem2 |= r2[m];
            if (lane == (sw & 31)) {
                if (sw < 32)      rem0 |= bit;
                else if (sw < 64) rem1 |= bit;
                else              rem2 |= bit;
            }
            if (nk == POST) break;
        }
    }

    __syncwarp();
    for (int k = nk + lane; k < POST; k += 32) s_keep[k] = 0;
    __syncwarp();
    for (int k = lane; k < POST; k += 32) {
        float4 b = g_top[s_keep[k]];
        out[k * 5 + 0] = 0.f;
        out[k * 5 + 1] = b.x;
        out[k * 5 + 2] = b.y;
        out[k * 5 + 3] = b.z;
        out[k * 5 + 4] = b.w;
    }
}

__global__ void k_nms(float* __restrict__ out) {
    __shared__ int s_keep[POST];
    nms_run(out, s_keep);
}

// Probe: identical work on the PREVIOUS replay's g_mask/g_top (deterministic
// across timed replays). Output goes to scratch; real k_nms overwrites d_out.
// Exists so the ncu capture slot (4th launch) lands on the NMS kernel.
__global__ void k_nms_probe() {
    __shared__ int s_keep[POST];
    nms_run(g_probe, s_keep);
}

// ---------------------------------------------------------------- launch
extern "C" void kernel_launch(void* const* d_in, const int* in_sizes, int n_in,
                              void* d_out, int out_size) {
    const float* cls  = (const float*)d_in[0];
    const float* bbox = (const float*)d_in[1];
    const int*   ih   = (const int*)d_in[2];
    const int*   iw   = (const int*)d_in[3];
    float* out = (float*)d_out;

    k_decode   <<<(NA + 255) / 256, 256>>>(cls, bbox, ih, iw);
    k_thresh   <<<1, 1024>>>();
    k_compact  <<<(NA + 255) / 256, 256>>>();
    k_nms_probe<<<1, 32>>>();                       // 4th launch = ncu capture slot
    k_rank2d   <<<dim3(CAP / 256, CAP / 256), 256>>>();
    k_scatter  <<<CAP / 256, 256>>>();
    k_mask     <<<dim3(NW, NW), 64>>>();
    k_nms      <<<1, 32>>>(out);
}

// round 11
// speedup vs baseline: 1.4082x; 1.4082x over previous
#include <cuda_runtime.h>
#include <cstdint>

#define NA    57600     // 64*100*9 anchors
#define NLOC  6400      // 64*100
#define FW    100
#define PRE   6000
#define POST  300
#define NW    94        // ceil(6000/64) u64 words
#define CAP   8192
#define NBIN  65536
#define NCO   1024
#define FULL  0xFFFFFFFFu
#define QD    16        // candidates per batch

typedef unsigned long long u64;

// Base anchors (ratios 0.5,1,2 x scales 8,16,32), numpy banker's rounding baked in.
__constant__ float c_base[36] = {
  -84.f,  -40.f,  99.f,  55.f,
 -176.f,  -88.f, 191.f, 103.f,
 -360.f, -184.f, 375.f, 199.f,
  -56.f,  -56.f,  71.f,  71.f,
 -120.f, -120.f, 135.f, 135.f,
 -248.f, -248.f, 263.f, 263.f,
  -36.f,  -80.f,  51.f,  95.f,
  -80.f, -168.f,  95.f, 183.f,
 -168.f, -344.f, 183.f, 359.f
};

// NOTE: g_hist/g_coarse/g_rank/g_cnt must be ZERO on entry to each run.
// They start zero (static init) and are re-zeroed by k_mask each run.
__device__ float4   g_boxes[NA];
__device__ unsigned g_keys[NA];
__device__ unsigned g_hist[NBIN];
__device__ unsigned g_coarse[NCO];
__device__ int      g_cnt;
__device__ unsigned g_B;
__device__ u64      g_cand[CAP];
__device__ int      g_rank[CAP];
__device__ float4   g_top[PRE];
__device__ u64      g_mask[(size_t)PRE * NW];   // triangular: words < i/64 of row i NOT written

// ---------------------------------------------------------------- decode + fine/coarse histograms
__global__ void k_decode(const float* __restrict__ cls,
                         const float* __restrict__ bbox,
                         const int*   __restrict__ ih,
                         const int*   __restrict__ iw) {
    int t = blockIdx.x * blockDim.x + threadIdx.x;
    if (t >= NA) return;
    int a = t / NLOC, loc = t % NLOC;       // coalesced channel reads
    int y = loc / FW, x = loc % FW;
    int ai = loc * 9 + a;                   // reference anchor index

    float s0 = cls[(2 * a)     * NLOC + loc];
    float s1 = cls[(2 * a + 1) * NLOC + loc];
    float m  = fmaxf(s0, s1);
    float e0 = expf(s0 - m), e1 = expf(s1 - m);
    float score = e1 / (e0 + e1);

    float dx = bbox[(4 * a + 0) * NLOC + loc];
    float dy = bbox[(4 * a + 1) * NLOC + loc];
    float dw = bbox[(4 * a + 2) * NLOC + loc];
    float dh = bbox[(4 * a + 3) * NLOC + loc];

    float sx = (float)(x * 16), sy = (float)(y * 16);
    float ax1 = sx + c_base[a * 4 + 0];
    float ay1 = sy + c_base[a * 4 + 1];
    float ax2 = sx + c_base[a * 4 + 2];
    float ay2 = sy + c_base[a * 4 + 3];

    float w  = ax2 - ax1 + 1.0f;
    float h  = ay2 - ay1 + 1.0f;
    float cx = ax1 + 0.5f * w;
    float cy = ay1 + 0.5f * h;

    float pcx = dx * w + cx;
    float pcy = dy * h + cy;
    float pw  = expf(dw) * w;
    float ph  = expf(dh) * h;

    float W = (float)(iw[0] - 1);
    float H = (float)(ih[0] - 1);
    float x1 = fminf(fmaxf(pcx - 0.5f * pw, 0.f), W);
    float y1 = fminf(fmaxf(pcy - 0.5f * ph, 0.f), H);
    float x2 = fminf(fmaxf(pcx + 0.5f * pw, 0.f), W);
    float y2 = fminf(fmaxf(pcy + 0.5f * ph, 0.f), H);

    bool valid = (x2 - x1 + 1.f >= 16.f) && (y2 - y1 + 1.f >= 16.f);
    float s = valid ? score : -1e30f;

    unsigned u = __float_as_uint(s);
    unsigned key = (u & 0x80000000u) ? ~u : (u | 0x80000000u);

    g_keys[t]   = key;
    g_boxes[ai] = make_float4(x1, y1, x2, y2);
    atomicAdd(&g_hist[key >> 16], 1u);
    atomicAdd(&g_coarse[key >> 22], 1u);
}

// ---------------------------------------------------------------- threshold bin via coarse hist (1 block)
__global__ void k_thresh() {
    __shared__ unsigned warpsum[32];
    __shared__ unsigned warpsuf[32];
    int t = threadIdx.x;            // 1024 threads, one per coarse bucket
    int lane = t & 31, warp = t >> 5;

    unsigned c = g_coarse[t];

    unsigned suf = c;
    #pragma unroll
    for (int off = 1; off < 32; off <<= 1) {
        unsigned v = __shfl_down_sync(FULL, suf, off);
        if (lane + off < 32) suf += v;
    }
    if (lane == 0) warpsum[warp] = suf;
    __syncthreads();
    if (warp == 0) {
        unsigned ws = warpsum[lane];
        unsigned s2 = ws;
        #pragma unroll
        for (int off = 1; off < 32; off <<= 1) {
            unsigned v = __shfl_down_sync(FULL, s2, off);
            if (lane + off < 32) s2 += v;
        }
        warpsuf[lane] = s2 - ws;
    }
    __syncthreads();

    unsigned suffInc = suf + warpsuf[warp];
    unsigned above   = suffInc - c;
    if (above < PRE && suffInc >= PRE) {
        unsigned run = above;
        int base = t * 64;          // coarse bucket t = fine bins [t*64, t*64+64)
        for (int b = 63; b >= 0; b--) {
            run += g_hist[base + b];
            if (run >= PRE) { g_B = (unsigned)(base + b); break; }
        }
    }
}

// ---------------------------------------------------------------- compact candidates (bin >= threshold bin)
__global__ void k_compact() {
    int t = blockIdx.x * blockDim.x + threadIdx.x;
    if (t >= NA) return;
    unsigned key = g_keys[t];
    if ((key >> 16) >= g_B) {
        int p = atomicAdd(&g_cnt, 1);
        if (p < CAP) {
            int a = t / NLOC, loc = t % NLOC;
            unsigned ai = (unsigned)(loc * 9 + a);
            g_cand[p] = ((u64)key << 32) | (~ai);
        }
    }
}

// ---------------------------------------------------------------- 2D-parallel exact rank (partial counts via atomics)
__global__ void k_rank2d() {
    __shared__ u64 tile[256];
    int cnt = g_cnt; if (cnt > CAP) cnt = CAP;
    if (blockIdx.x * 256 >= cnt || blockIdx.y * 256 >= cnt) return;  // uniform early exit
    int j = blockIdx.y * 256 + threadIdx.x;
    tile[threadIdx.x] = (j < cnt) ? g_cand[j] : 0ULL;   // zeros never beat valid keys
    __syncthreads();
    int p = blockIdx.x * 256 + threadIdx.x;
    if (p >= cnt) return;
    u64 v = g_cand[p];
    int r = 0;
    #pragma unroll 8
    for (int q = 0; q < 256; q++) r += (tile[q] > v);
    if (r) atomicAdd(&g_rank[p], r);
}

// ---------------------------------------------------------------- scatter boxes to rank order
__global__ void k_scatter() {
    int cnt = g_cnt; if (cnt > CAP) cnt = CAP;
    int p = blockIdx.x * 256 + threadIdx.x;
    if (p >= cnt) return;
    int r = g_rank[p];
    if (r < PRE) {
        u64 v = g_cand[p];
        unsigned idx = ~(unsigned)v;
        g_top[r] = g_boxes[idx];
    }
}

// ---------------------------------------------------------------- IoU bitmask (upper-triangular) + state re-zero
__global__ void k_mask() {
    __shared__ float4 sb[64];
    int cb = blockIdx.x, rb = blockIdx.y, t = threadIdx.x;

    // housekeeping for the NEXT run: zero hist/coarse/rank/cnt (safe: all
    // consumers of these ran in earlier kernels of THIS run)
    {
        int bid = blockIdx.y * gridDim.x + blockIdx.x;
        int gt  = bid * 64 + t;
        if (gt < NBIN)                       g_hist[gt] = 0u;
        else if (gt < NBIN + NCO)            g_coarse[gt - NBIN] = 0u;
        else if (gt < NBIN + NCO + CAP)      g_rank[gt - NBIN - NCO] = 0;
        else if (gt == NBIN + NCO + CAP)     g_cnt = 0;
    }

    if (cb < rb) return;           // sub-diagonal: never written, never read
    int i = rb * 64 + t;
    int j0 = cb * 64;
    int jg = j0 + t;
    sb[t] = (jg < PRE) ? g_top[jg] : make_float4(0.f, 0.f, 0.f, 0.f);
    __syncthreads();
    if (i >= PRE) return;
    float4 bi = g_top[i];
    float ai = (bi.z - bi.x) * (bi.w - bi.y);
    u64 bits = 0ULL;
    #pragma unroll 4
    for (int b = 0; b < 64; b++) {
        int j = j0 + b;
        float4 bj = sb[b];
        float aj = (bj.z - bj.x) * (bj.w - bj.y);
        float lx = fmaxf(bi.x, bj.x), ly = fmaxf(bi.y, bj.y);
        float rx = fminf(bi.z, bj.z), ry = fminf(bi.w, bj.w);
        float ww = fmaxf(rx - lx, 0.f), hh = fmaxf(ry - ly, 0.f);
        float inter = ww * hh;
        float iou = inter / (ai + aj - inter);
        if (j > i && j < PRE && iou > 0.7f) bits |= 1ULL << b;
    }
    g_mask[(size_t)i * NW + cb] = bits;
}

// ================================================================ warp-specialized NMS
// 128 threads. Warp 0 = decider (bitmap in registers). Warps 1-3 = prefetchers
// (stage candidate mask rows into double-buffered smem). Exact greedy order:
// cursor-monotone extraction + decide-time re-check (same semantics as the
// verified pipelined version).
__global__ __launch_bounds__(128) void k_nms(float* __restrict__ out) {
    __shared__ u64 srow[2][QD][96];     // staged rows (words >= NW or < rowstart zeroed)
    __shared__ int scand[2][QD];
    __shared__ int swsel[2][2];         // the two words candidates were drawn from
    __shared__ int scnt[2];
    __shared__ int s_nk;
    __shared__ int s_keep[POST];

    int tid  = threadIdx.x;
    int lane = tid & 31;
    int wid  = tid >> 5;

    for (int k = tid; k < POST; k += 128) s_keep[k] = 0;
    if (tid == 0) { s_nk = 0; scnt[0] = 0; scnt[1] = 0; }

    // decider state (warp 0 registers)
    u64 rem0 = 0ULL, rem1 = 0ULL, rem2 = 0ULL;
    if (lane == 29) rem2 = (~0ULL) << 48;   // word 93: indices 6000..6015 invalid
    if (lane >= 30) rem2 = ~0ULL;           // words 94,95 don't exist
    int cursor = 0;
    int nk = 0;

    // ---- extraction: up to QD lowest free indices >= cursor from first 2 free words
    auto extract = [&](int buf) {
        u64 m0 = ~rem0, m1 = ~rem1, m2 = ~rem2;
        int cw = cursor >> 6, cbit = cursor & 63;
        if (lane < cw)            m0 = 0ULL; else if (lane == cw)      m0 &= (~0ULL) << cbit;
        if (lane + 32 < cw)       m1 = 0ULL; else if (lane + 32 == cw) m1 &= (~0ULL) << cbit;
        if (lane + 64 < cw)       m2 = 0ULL; else if (lane + 64 == cw) m2 &= (~0ULL) << cbit;
        unsigned b0 = __ballot_sync(FULL, m0 != 0ULL);
        unsigned b1 = __ballot_sync(FULL, m1 != 0ULL);
        unsigned b2 = __ballot_sync(FULL, m2 != 0ULL);

        int w1 = -1, w2 = -1; u64 f1 = 0ULL, f2 = 0ULL;
        if (b0)      { int s = __ffs(b0) - 1; w1 = s;      f1 = __shfl_sync(FULL, m0, s); b0 &= b0 - 1; }
        else if (b1) { int s = __ffs(b1) - 1; w1 = s + 32; f1 = __shfl_sync(FULL, m1, s); b1 &= b1 - 1; }
        else if (b2) { int s = __ffs(b2) - 1; w1 = s + 64; f1 = __shfl_sync(FULL, m2, s); b2 &= b2 - 1; }
        if (w1 >= 0) {
            if (b0)      { int s = __ffs(b0) - 1; w2 = s;      f2 = __shfl_sync(FULL, m0, s); }
            else if (b1) { int s = __ffs(b1) - 1; w2 = s + 32; f2 = __shfl_sync(FULL, m1, s); }
            else if (b2) { int s = __ffs(b2) - 1; w2 = s + 64; f2 = __shfl_sync(FULL, m2, s); }
        }

        int j[QD];
        u64 t1 = f1, t2 = f2;
        int cnt = 0;
        #pragma unroll
        for (int m = 0; m < QD; m++) {
            if (t1) {
                int b = __ffsll((long long)t1) - 1;
                j[m] = (w1 << 6) + b; t1 &= t1 - 1; cnt++;
            } else if (t2) {
                int b = __ffsll((long long)t2) - 1;
                j[m] = (w2 << 6) + b; t2 &= t2 - 1; cnt++;
            } else j[m] = PRE;
        }
        if (cnt) cursor = j[cnt - 1] + 1;
        if (lane == 0) {
            #pragma unroll
            for (int m = 0; m < QD; m++) scand[buf][m] = j[m];
            swsel[buf][0] = w1; swsel[buf][1] = w2;
            scnt[buf] = cnt;
        }
    };

    // ---- decide: process staged batch in ascending order against live bitmap
    auto decide = [&](int buf) {
        if (scnt[buf] == 0) return;
        int w1 = swsel[buf][0], w2 = swsel[buf][1];
        // fresh uniform copies of the two words
        u64 vsel1 = (w1 < 32) ? rem0 : ((w1 < 64) ? rem1 : rem2);
        u64 remw1 = __shfl_sync(FULL, vsel1, w1 & 31);
        u64 remw2 = ~0ULL;
        if (w2 >= 0) {
            u64 vsel2 = (w2 < 32) ? rem0 : ((w2 < 64) ? rem1 : rem2);
            remw2 = __shfl_sync(FULL, vsel2, w2 & 31);
        }
        #pragma unroll
        for (int m = 0; m < QD; m++) {
            int jm = scand[buf][m];            // broadcast LDS
            if (jm >= PRE) break;
            int sw = jm >> 6;
            u64 bit = 1ULL << (jm & 63);
            bool inW1 = (sw == w1);
            if ((inW1 ? remw1 : remw2) & bit) continue;   // suppressed

            if (lane == 0) s_keep[nk] = jm;
            nk++;

            u64 v0 = srow[buf][m][lane];
            u64 v1 = srow[buf][m][lane + 32];
            u64 v2 = srow[buf][m][lane + 64];
            rem0 |= v0; rem1 |= v1; rem2 |= v2;
            remw1 |= srow[buf][m][w1];         // uniform broadcast LDS
            if (w2 >= 0) remw2 |= srow[buf][m][w2];
            if (inW1) remw1 |= bit; else remw2 |= bit;
            if (lane == (sw & 31)) {
                if (sw < 32)      rem0 |= bit;
                else if (sw < 64) rem1 |= bit;
                else              rem2 |= bit;
            }
            if (nk == POST) break;
        }
        if (lane == 0) s_nk = nk;
    };

    // preamble: stage first batch list
    if (wid == 0) extract(0);
    __syncthreads();

    int cur = 0;
    for (;;) {
        int other = cur ^ 1;
        if (wid > 0) {
            // prefetch rows for batch `cur` into smem (off the critical warp)
            int tp = tid - 32;                 // 0..95
            #pragma unroll
            for (int m = 0; m < QD; m++) {
                int jm = scand[cur][m];        // broadcast LDS
                if (jm < PRE) {
                    int sw = jm >> 6;
                    u64 v = (tp >= sw && tp < NW) ? g_mask[(size_t)jm * NW + tp] : 0ULL;
                    srow[cur][m][tp] = v;
                }
            }
        } else {
            decide(other);                     // consume batch staged last iteration
            if (lane == 0) scnt[other] = 0;    // mark consumed
            if (nk < POST) extract(other);     // refill list for next staging
        }
        __syncthreads();
        if (s_nk >= POST) break;
        if (scnt[0] == 0 && scnt[1] == 0) break;
        cur ^= 1;
    }

    __syncthreads();
    for (int k = tid; k < POST; k += 128) {
        float4 b = g_top[s_keep[k]];
        out[k * 5 + 0] = 0.f;
        out[k * 5 + 1] = b.x;
        out[k * 5 + 2] = b.y;
        out[k * 5 + 3] = b.z;
        out[k * 5 + 4] = b.w;
    }
}

// ---------------------------------------------------------------- launch
extern "C" void kernel_launch(void* const* d_in, const int* in_sizes, int n_in,
                              void* d_out, int out_size) {
    const float* cls  = (const float*)d_in[0];
    const float* bbox = (const float*)d_in[1];
    const int*   ih   = (const int*)d_in[2];
    const int*   iw   = (const int*)d_in[3];
    float* out = (float*)d_out;

    k_decode <<<(NA + 255) / 256, 256>>>(cls, bbox, ih, iw);
    k_thresh <<<1, 1024>>>();
    k_compact<<<(NA + 255) / 256, 256>>>();
    k_rank2d <<<dim3(CAP / 256, CAP / 256), 256>>>();
    k_scatter<<<CAP / 256, 256>>>();
    k_mask   <<<dim3(NW, NW), 64>>>();
    k_nms    <<<1, 128>>>(out);
}